// round 9
// baseline (speedup 1.0000x reference)
#include <cuda_runtime.h>
#include <cuda_bf16.h>
#include <math.h>
#include <stdint.h>

#define BB 32
#define NREG 196
#define EE 512
#define HH 512
#define SEQ 64
#define VV 32000

#define NBLK 148
#define NTHR 512

// ---------------- scratch (device globals; no allocations) ----------------
__device__ float g_fmean[BB * EE];
__device__ __align__(16) float g_hbuf[2][BB * HH];   // [b][k]   (attention)
__device__ __align__(16) float g_hT[2][HH * BB];     // [k][b]   (gate GEMV)
__device__ float g_cT[HH * BB];                      // [k][b]
__device__ __align__(16) float g_actCE[2 * EE * BB]; // [k][b]: k<512 ctx, k>=512 emb*sqrtE
__device__ __align__(16) float g_actX[EE * BB];      // [k][b]: x
__device__ __align__(16) float g_Hall[SEQ * BB * HH];// row (t*32+b)
__device__ unsigned g_bar_count;
__device__ unsigned g_bar_gen;

// bf16 split buffers for tensor-core GEMM
__device__ __align__(16) __nv_bfloat16 g_AH[SEQ * BB * HH];
__device__ __align__(16) __nv_bfloat16 g_AL[SEQ * BB * HH];
__device__ __align__(16) __nv_bfloat16 g_WH[(size_t)VV * EE];
__device__ __align__(16) __nv_bfloat16 g_WL[(size_t)VV * EE];

// ---------------- grid-wide barrier ----------------
__device__ __forceinline__ void gridbar() {
    __syncthreads();
    if (threadIdx.x == 0) {
        unsigned gen = *((volatile unsigned*)&g_bar_gen);
        __threadfence();
        if (atomicAdd(&g_bar_count, 1u) == (unsigned)(gridDim.x - 1)) {
            g_bar_count = 0;
            __threadfence();
            atomicAdd(&g_bar_gen, 1u);
        } else {
            while (*((volatile unsigned*)&g_bar_gen) == gen) { __nanosleep(32); }
        }
        __threadfence();
    }
    __syncthreads();
}

__device__ __forceinline__ float warpsum(float v) {
#pragma unroll
    for (int o = 16; o; o >>= 1) v += __shfl_xor_sync(0xffffffffu, v, o);
    return v;
}

__device__ __forceinline__ float warpdot512(const float* __restrict__ a,
                                            const float* __restrict__ b, int lane) {
    float s = 0.f;
#pragma unroll
    for (int c = 0; c < 4; c++) {
        float4 av = *(const float4*)(a + c * 128 + lane * 4);
        float4 bv = *(const float4*)(b + c * 128 + lane * 4);
        s += av.x * bv.x + av.y * bv.y + av.z * bv.z + av.w * bv.w;
    }
    return s;
}

// smem pool layout (floats):
// P12:  h[512] @0 | sc[256] @512 | attn[256] @768 | red[32] @1024 | part[16*512] @1056
// GEMV: act[4096] @0 | w[2048] @4096 | red[2048] @6144 | out[512] @8192
#define POOL_F 9248

// ---------------- persistent recurrence kernel ----------------
__global__ void __launch_bounds__(NTHR) recurrence_kernel(
    const float* __restrict__ features, const int* __restrict__ captions,
    const float* __restrict__ embed_W,
    const float* __restrict__ ihW, const float* __restrict__ ihb,
    const float* __restrict__ icW, const float* __restrict__ icb,
    const float* __restrict__ rW,  const float* __restrict__ rb,
    const float* __restrict__ Wih, const float* __restrict__ Whh,
    const float* __restrict__ bih, const float* __restrict__ bhh)
{
    const int tid  = threadIdx.x;
    const int lane = tid & 31;
    const int w    = tid >> 5;
    const int gtid = blockIdx.x * NTHR + tid;
    const int wid_g  = gtid >> 5;
    const int nwarps = (NBLK * NTHR) >> 5;
    const int gstride = NBLK * NTHR;

    __shared__ __align__(16) float pool[POOL_F];
    float* sh_h   = pool;            // 512
    float* sSc    = pool + 512;      // 256
    float* sAttn  = pool + 768;      // 256
    float* sRedS  = pool + 1024;     // 32
    float* sPart  = pool + 1056;     // 8192
    float* sAct   = pool;            // 4096
    float* sW     = pool + 4096;     // 2048
    float* sRed   = pool + 6144;     // 2048
    float* sOut   = pool + 8192;     // 512

    // ---- init a: fmean
    for (int idx = gtid; idx < BB * EE; idx += gstride) {
        int b = idx >> 9, e = idx & 511;
        const float* fp = features + (size_t)b * NREG * EE + e;
        float s = 0.f;
        for (int n = 0; n < NREG; n++) s += fp[n * EE];
        g_fmean[idx] = s * (1.0f / NREG);
    }
    gridbar();

    // ---- init b: h0 / c0 (warp per output)
    for (int task = wid_g; task < 2 * BB * HH; task += nwarps) {
        int which = task & 1;
        int m = task >> 1;
        int b = m >> 9, eo = m & 511;
        const float* Wrow = (which ? icW : ihW) + (size_t)eo * EE;
        float s = warpsum(warpdot512(Wrow, g_fmean + b * EE, lane));
        if (lane == 0) {
            if (which) {
                g_cT[eo * BB + b] = s + icb[eo];
            } else {
                float hv = s + ihb[eo];
                g_hbuf[0][m] = hv;
                g_hT[0][eo * BB + b] = hv;
            }
        }
    }
    gridbar();

    for (int t = 0; t < SEQ; t++) {
        const float* h_cur  = g_hbuf[t & 1];
        const float* hT_cur = g_hT[t & 1];
        float*       h_nxt  = g_hbuf[(t & 1) ^ 1];
        float*       hT_nxt = g_hT[(t & 1) ^ 1];

        // ==== P12: attention (32 blocks, one per batch, no redundancy) + emb fill
        if (blockIdx.x < BB) {
            const int b = blockIdx.x;
            const float* fb = features + (size_t)b * NREG * EE;

            sh_h[tid] = h_cur[b * EE + tid];
            __syncthreads();

            // scores (each computed once)
            for (int n = w; n < NREG; n += 16) {
                float s = warpsum(warpdot512(fb + (size_t)n * EE, sh_h, lane));
                if (lane == 0) sSc[n] = s;
            }
            __syncthreads();

            // softmax over 196
            float v = (tid < NREG) ? sSc[tid] : -1e30f;
            float m = v;
#pragma unroll
            for (int o = 16; o; o >>= 1) m = fmaxf(m, __shfl_xor_sync(0xffffffffu, m, o));
            if (lane == 0) sRedS[w] = m;
            __syncthreads();
            float mx = sRedS[0];
#pragma unroll
            for (int i = 1; i < 16; i++) mx = fmaxf(mx, sRedS[i]);
            float ev = (tid < NREG) ? __expf(v - mx) : 0.f;
            float ps = warpsum(ev);
            __syncthreads();
            if (lane == 0) sRedS[w] = ps;
            __syncthreads();
            float tot = 0.f;
#pragma unroll
            for (int i = 0; i < 16; i++) tot += sRedS[i];
            if (tid < NREG) sAttn[tid] = ev / tot;
            __syncthreads();

            // context: warp handles n-subset for ALL 512 cols (16 floats/lane)
            float4 a0 = make_float4(0.f, 0.f, 0.f, 0.f);
            float4 a1 = a0, a2 = a0, a3 = a0;
            for (int n = w; n < NREG; n += 16) {
                float a = sAttn[n];
                const float* fr = fb + (size_t)n * EE + lane * 4;
                float4 f0 = *(const float4*)(fr + 0 * 128);
                float4 f1 = *(const float4*)(fr + 1 * 128);
                float4 f2 = *(const float4*)(fr + 2 * 128);
                float4 f3 = *(const float4*)(fr + 3 * 128);
                a0.x += a * f0.x; a0.y += a * f0.y; a0.z += a * f0.z; a0.w += a * f0.w;
                a1.x += a * f1.x; a1.y += a * f1.y; a1.z += a * f1.z; a1.w += a * f1.w;
                a2.x += a * f2.x; a2.y += a * f2.y; a2.z += a * f2.z; a2.w += a * f2.w;
                a3.x += a * f3.x; a3.y += a * f3.y; a3.z += a * f3.z; a3.w += a * f3.w;
            }
            float* pp = sPart + w * 512 + lane * 4;
            *(float4*)(pp + 0 * 128) = a0;
            *(float4*)(pp + 1 * 128) = a1;
            *(float4*)(pp + 2 * 128) = a2;
            *(float4*)(pp + 3 * 128) = a3;
            __syncthreads();
            {
                float s = 0.f;
#pragma unroll
                for (int i = 0; i < 16; i++) s += sPart[i * 512 + tid];
                g_actCE[tid * BB + b] = s;
            }
        } else {
            // emb fill (116 blocks)
            for (int idx = (blockIdx.x - BB) * NTHR + tid; idx < BB * EE;
                 idx += (NBLK - BB) * NTHR) {
                int b = idx >> 9, k = idx & 511;
                int tok = captions[b * SEQ + t];
                g_actCE[(EE + k) * BB + b] =
                    embed_W[(size_t)tok * EE + k] * 22.62741699796952f; // sqrt(512)
            }
        }
        gridbar();

        // ==== P3: x = rW @ [ctx; emb] + rb  (128 blocks x 4 rows; warp=(row, kq))
        if (blockIdx.x < 128) {
            const int r0 = blockIdx.x * 4;
            const int rl = w >> 2, qq = w & 3;
            float acc = 0.f;
            for (int kc = 0; kc < 8; kc++) {
                __syncthreads();
                const float* asrc = g_actCE + kc * 128 * BB;
                for (int i4 = tid; i4 < 1024; i4 += NTHR)
                    ((float4*)sAct)[i4] = ((const float4*)asrc)[i4];
                {
                    int r = tid >> 7, k = tid & 127;
                    sW[tid] = rW[(size_t)(r0 + r) * (EE + HH) + kc * 128 + k];
                }
                __syncthreads();
                const float* wp = sW + rl * 128 + qq * 32;
#pragma unroll
                for (int k4 = 0; k4 < 32; k4 += 4) {
                    float4 wv = *(const float4*)(wp + k4);
                    const float* ap = sAct + (qq * 32 + k4) * BB + lane;
                    acc += wv.x * ap[0 * BB];
                    acc += wv.y * ap[1 * BB];
                    acc += wv.z * ap[2 * BB];
                    acc += wv.w * ap[3 * BB];
                }
            }
            sRed[(rl * 4 + qq) * BB + lane] = acc;
            __syncthreads();
            if (tid < 128) {
                int r = tid >> 5, b = tid & 31;
                float s = sRed[(r * 4 + 0) * BB + b] + sRed[(r * 4 + 1) * BB + b]
                        + sRed[(r * 4 + 2) * BB + b] + sRed[(r * 4 + 3) * BB + b];
                g_actX[(r0 + r) * BB + b] = s + rb[r0 + r];
            }
        }
        gridbar();

        // ==== P4: gates + cell (128 blocks x 16 rows'; warp = (4-row group, kq))
        if (blockIdx.x < 128) {
            const int rp0 = blockIdx.x * 16;
            const int rg = w >> 2, qq = w & 3;
            float acc0 = 0.f, acc1 = 0.f, acc2 = 0.f, acc3 = 0.f;
            for (int kc = 0; kc < 8; kc++) {
                __syncthreads();
                const float* asrc = (kc < 4) ? (g_actX + kc * 128 * BB)
                                             : (hT_cur + (kc - 4) * 128 * BB);
                for (int i4 = tid; i4 < 1024; i4 += NTHR)
                    ((float4*)sAct)[i4] = ((const float4*)asrc)[i4];
#pragma unroll
                for (int s = 0; s < 4; s++) {
                    int i = tid + s * NTHR;
                    int rl = i >> 7, k = i & 127;
                    int rp = rp0 + rl;
                    int hi = rp >> 2, gate = rp & 3;
                    sW[i] = (kc < 4)
                        ? Wih[(size_t)(gate * HH + hi) * EE + kc * 128 + k]
                        : Whh[(size_t)(gate * HH + hi) * HH + (kc - 4) * 128 + k];
                }
                __syncthreads();
                const float* w0p = sW + (rg * 4 + 0) * 128 + qq * 32;
                const float* w1p = sW + (rg * 4 + 1) * 128 + qq * 32;
                const float* w2p = sW + (rg * 4 + 2) * 128 + qq * 32;
                const float* w3p = sW + (rg * 4 + 3) * 128 + qq * 32;
#pragma unroll
                for (int k4 = 0; k4 < 32; k4 += 4) {
                    const float* ap = sAct + (qq * 32 + k4) * BB + lane;
                    float a0 = ap[0 * BB], a1 = ap[1 * BB];
                    float a2 = ap[2 * BB], a3 = ap[3 * BB];
                    float4 w0 = *(const float4*)(w0p + k4);
                    float4 w1 = *(const float4*)(w1p + k4);
                    float4 w2 = *(const float4*)(w2p + k4);
                    float4 w3 = *(const float4*)(w3p + k4);
                    acc0 += w0.x * a0 + w0.y * a1 + w0.z * a2 + w0.w * a3;
                    acc1 += w1.x * a0 + w1.y * a1 + w1.z * a2 + w1.w * a3;
                    acc2 += w2.x * a0 + w2.y * a1 + w2.z * a2 + w2.w * a3;
                    acc3 += w3.x * a0 + w3.y * a1 + w3.z * a2 + w3.w * a3;
                }
            }
            sRed[((rg * 4 + 0) * 4 + qq) * BB + lane] = acc0;
            sRed[((rg * 4 + 1) * 4 + qq) * BB + lane] = acc1;
            sRed[((rg * 4 + 2) * 4 + qq) * BB + lane] = acc2;
            sRed[((rg * 4 + 3) * 4 + qq) * BB + lane] = acc3;
            __syncthreads();
            {
                int rl = tid >> 5, b = tid & 31;
                float s = sRed[(rl * 4 + 0) * BB + b] + sRed[(rl * 4 + 1) * BB + b]
                        + sRed[(rl * 4 + 2) * BB + b] + sRed[(rl * 4 + 3) * BB + b];
                sOut[rl * BB + b] = s;
            }
            __syncthreads();
            if (tid < 128) {
                int hl = tid >> 5;
                int b  = tid & 31;
                int hi = blockIdx.x * 4 + hl;
                float iv = sOut[(hl * 4 + 0) * BB + b] + bih[hi]          + bhh[hi];
                float fv = sOut[(hl * 4 + 1) * BB + b] + bih[HH + hi]     + bhh[HH + hi];
                float gv = sOut[(hl * 4 + 2) * BB + b] + bih[2 * HH + hi] + bhh[2 * HH + hi];
                float ov = sOut[(hl * 4 + 3) * BB + b] + bih[3 * HH + hi] + bhh[3 * HH + hi];
                float si = 1.f / (1.f + __expf(-iv));
                float sf = 1.f / (1.f + __expf(-fv));
                float so = 1.f / (1.f + __expf(-ov));
                float c2 = sf * g_cT[hi * BB + b] + si * tanhf(gv);
                float h2 = so * tanhf(c2);
                g_cT[hi * BB + b] = c2;
                hT_nxt[hi * BB + b] = h2;
                h_nxt[b * HH + hi] = h2;
                g_Hall[((size_t)t * BB + b) * HH + hi] = h2;
            }
        }
        gridbar();
    }
}

// ---------------- fp32 -> bf16 hi/lo split ----------------
__device__ __forceinline__ void split_store(float4 v, __nv_bfloat16* H,
                                            __nv_bfloat16* L, size_t off) {
    __nv_bfloat162 h0, h1, l0, l1;
    h0.x = __float2bfloat16(v.x); h0.y = __float2bfloat16(v.y);
    h1.x = __float2bfloat16(v.z); h1.y = __float2bfloat16(v.w);
    l0.x = __float2bfloat16(v.x - __bfloat162float(h0.x));
    l0.y = __float2bfloat16(v.y - __bfloat162float(h0.y));
    l1.x = __float2bfloat16(v.z - __bfloat162float(h1.x));
    l1.y = __float2bfloat16(v.w - __bfloat162float(h1.y));
    *(__nv_bfloat162*)(H + off) = h0; *(__nv_bfloat162*)(H + off + 2) = h1;
    *(__nv_bfloat162*)(L + off) = l0; *(__nv_bfloat162*)(L + off + 2) = l1;
}

__global__ void __launch_bounds__(256) convert_kernel(const float* __restrict__ outW)
{
    const size_t NW4 = ((size_t)VV * EE) / 4;
    const size_t NA4 = ((size_t)SEQ * BB * HH) / 4;
    size_t stride = (size_t)gridDim.x * blockDim.x;
    for (size_t i = (size_t)blockIdx.x * blockDim.x + threadIdx.x;
         i < NW4 + NA4; i += stride) {
        if (i < NW4) {
            float4 v = ((const float4*)outW)[i];
            split_store(v, g_WH, g_WL, i * 4);
        } else {
            size_t j = i - NW4;
            float4 v = ((const float4*)g_Hall)[j];
            split_store(v, g_AH, g_AL, j * 4);
        }
    }
}

// ---------------- tensor-core output GEMM ----------------
#define LDSW 40  // padded smem row stride (bf16 elems)

__device__ __forceinline__ uint32_t s2u(const void* p) {
    return (uint32_t)__cvta_generic_to_shared(p);
}
__device__ __forceinline__ void ldsm_x4(uint32_t r[4], uint32_t addr) {
    asm volatile("ldmatrix.sync.aligned.m8n8.x4.shared.b16 {%0,%1,%2,%3}, [%4];"
                 : "=r"(r[0]), "=r"(r[1]), "=r"(r[2]), "=r"(r[3]) : "r"(addr));
}
__device__ __forceinline__ void mma_bf16(float c[4], const uint32_t a[4], const uint32_t b[2]) {
    asm volatile("mma.sync.aligned.m16n8k16.row.col.f32.bf16.bf16.f32 "
                 "{%0,%1,%2,%3}, {%4,%5,%6,%7}, {%8,%9}, {%0,%1,%2,%3};"
                 : "+f"(c[0]), "+f"(c[1]), "+f"(c[2]), "+f"(c[3])
                 : "r"(a[0]), "r"(a[1]), "r"(a[2]), "r"(a[3]), "r"(b[0]), "r"(b[1]));
}

__global__ void __launch_bounds__(256) out_gemm_tc(
    const float* __restrict__ outb, float* __restrict__ out)
{
    __shared__ __align__(16) __nv_bfloat16 sAH[128 * LDSW];
    __shared__ __align__(16) __nv_bfloat16 sAL[128 * LDSW];
    __shared__ __align__(16) __nv_bfloat16 sBH[128 * LDSW];
    __shared__ __align__(16) __nv_bfloat16 sBL[128 * LDSW];

    const int tid  = threadIdx.x;
    const int lane = tid & 31;
    const int w    = tid >> 5;
    const int wm   = w >> 2;
    const int wn   = w & 3;
    const int m0 = blockIdx.y * 128;
    const int n0 = blockIdx.x * 128;

    float acc[4][4][4];
#pragma unroll
    for (int mt = 0; mt < 4; mt++)
#pragma unroll
        for (int nt = 0; nt < 4; nt++)
#pragma unroll
            for (int r = 0; r < 4; r++) acc[mt][nt][r] = 0.f;

    const int a_row = lane & 15;
    const int a_k8  = (lane >> 4) * 8;
    const int b_nrw = (lane & 7) + ((lane >> 4) << 3);
    const int b_k8  = ((lane >> 3) & 1) * 8;

    const uint32_t uAH = s2u(sAH), uAL = s2u(sAL);
    const uint32_t uBH = s2u(sBH), uBL = s2u(sBL);

    for (int k0 = 0; k0 < 512; k0 += 32) {
        __syncthreads();
#pragma unroll
        for (int i = 0; i < 2; i++) {
            int v = tid + i * 256;
            int row = v >> 2;
            int kc  = (v & 3) * 8;
            size_t ga = (size_t)(m0 + row) * 512 + k0 + kc;
            size_t gb = (size_t)(n0 + row) * 512 + k0 + kc;
            int so = row * LDSW + kc;
            *(uint4*)(sAH + so) = *(const uint4*)(g_AH + ga);
            *(uint4*)(sAL + so) = *(const uint4*)(g_AL + ga);
            *(uint4*)(sBH + so) = *(const uint4*)(g_WH + gb);
            *(uint4*)(sBL + so) = *(const uint4*)(g_WL + gb);
        }
        __syncthreads();

#pragma unroll
        for (int ks = 0; ks < 32; ks += 16) {
            uint32_t aH[4][4], aL[4][4];
#pragma unroll
            for (int mt = 0; mt < 4; mt++) {
                int off = ((wm * 64 + mt * 16 + a_row) * LDSW + ks + a_k8) * 2;
                ldsm_x4(aH[mt], uAH + off);
                ldsm_x4(aL[mt], uAL + off);
            }
            uint32_t bH[4][2], bL[4][2];
#pragma unroll
            for (int p = 0; p < 2; p++) {
                int off = ((wn * 32 + p * 16 + b_nrw) * LDSW + ks + b_k8) * 2;
                uint32_t r[4];
                ldsm_x4(r, uBH + off);
                bH[2 * p][0] = r[0]; bH[2 * p][1] = r[1];
                bH[2 * p + 1][0] = r[2]; bH[2 * p + 1][1] = r[3];
                ldsm_x4(r, uBL + off);
                bL[2 * p][0] = r[0]; bL[2 * p][1] = r[1];
                bL[2 * p + 1][0] = r[2]; bL[2 * p + 1][1] = r[3];
            }
#pragma unroll
            for (int mt = 0; mt < 4; mt++)
#pragma unroll
                for (int nt = 0; nt < 4; nt++) {
                    mma_bf16(acc[mt][nt], aH[mt], bH[nt]);
                    mma_bf16(acc[mt][nt], aH[mt], bL[nt]);
                    mma_bf16(acc[mt][nt], aL[mt], bH[nt]);
                }
        }
    }

#pragma unroll
    for (int mt = 0; mt < 4; mt++) {
#pragma unroll
        for (int half = 0; half < 2; half++) {
            int m = m0 + wm * 64 + mt * 16 + (lane >> 2) + half * 8;
            int tt = m >> 5, b = m & 31;
            float* orow = out + ((size_t)b * SEQ + tt) * VV;
#pragma unroll
            for (int nt = 0; nt < 4; nt++) {
                int n = n0 + wn * 32 + nt * 8 + 2 * (lane & 3);
                float2 bias = *(const float2*)(outb + n);
                float2 v;
                v.x = acc[mt][nt][2 * half + 0] + bias.x;
                v.y = acc[mt][nt][2 * half + 1] + bias.y;
                *(float2*)(orow + n) = v;
            }
        }
    }
}

extern "C" void kernel_launch(void* const* d_in, const int* in_sizes, int n_in,
                              void* d_out, int out_size)
{
    const float* features = (const float*)d_in[0];
    const int*   captions = (const int*)d_in[1];
    const float* embed_W  = (const float*)d_in[2];
    const float* ihW = (const float*)d_in[3];
    const float* ihb = (const float*)d_in[4];
    const float* icW = (const float*)d_in[5];
    const float* icb = (const float*)d_in[6];
    const float* rW  = (const float*)d_in[7];
    const float* rb  = (const float*)d_in[8];
    const float* Wih = (const float*)d_in[9];
    const float* Whh = (const float*)d_in[10];
    const float* bih = (const float*)d_in[11];
    const float* bhh = (const float*)d_in[12];
    const float* outW = (const float*)d_in[13];
    const float* outb = (const float*)d_in[14];

    recurrence_kernel<<<NBLK, NTHR>>>(features, captions, embed_W,
                                      ihW, ihb, icW, icb, rW, rb,
                                      Wih, Whh, bih, bhh);
    convert_kernel<<<2048, 256>>>(outW);
    dim3 grid(VV / 128, (SEQ * BB) / 128);
    out_gemm_tc<<<grid, 256>>>(outb, (float*)d_out);
}

// round 10
// speedup vs baseline: 1.5498x; 1.5498x over previous
#include <cuda_runtime.h>
#include <cuda_bf16.h>
#include <math.h>
#include <stdint.h>

#define BB 32
#define NREG 196
#define EE 512
#define HH 512
#define SEQ 64
#define VV 32000

#define NBLK 148
#define NTHR 512

// ---------------- scratch (device globals; no allocations) ----------------
__device__ float g_fmean[BB * EE];
__device__ __align__(16) float g_hbuf[2][BB * HH];   // [b][k]   (attention)
__device__ __align__(16) float g_hT[2][HH * BB];     // [k][b]   (gate GEMV)
__device__ float g_cT[HH * BB];                      // [k][b]
__device__ __align__(16) float g_actCE[2 * EE * BB]; // [k][b]: k<512 ctx, k>=512 emb*sqrtE
__device__ __align__(16) float g_actX[EE * BB];      // [k][b]: x
__device__ __align__(16) float g_Hall[SEQ * BB * HH];// row (t*32+b)
__device__ unsigned g_bar_count;
__device__ unsigned g_bar_gen;

// bf16 split buffers for tensor-core GEMM
__device__ __align__(16) __nv_bfloat16 g_AH[SEQ * BB * HH];
__device__ __align__(16) __nv_bfloat16 g_AL[SEQ * BB * HH];
__device__ __align__(16) __nv_bfloat16 g_WH[(size_t)VV * EE];
__device__ __align__(16) __nv_bfloat16 g_WL[(size_t)VV * EE];

// ---------------- grid-wide barrier ----------------
__device__ __forceinline__ void gridbar() {
    __syncthreads();
    if (threadIdx.x == 0) {
        unsigned gen = *((volatile unsigned*)&g_bar_gen);
        __threadfence();
        if (atomicAdd(&g_bar_count, 1u) == (unsigned)(gridDim.x - 1)) {
            g_bar_count = 0;
            __threadfence();
            atomicAdd(&g_bar_gen, 1u);
        } else {
            while (*((volatile unsigned*)&g_bar_gen) == gen) { __nanosleep(32); }
        }
        __threadfence();
    }
    __syncthreads();
}

__device__ __forceinline__ float warpsum(float v) {
#pragma unroll
    for (int o = 16; o; o >>= 1) v += __shfl_xor_sync(0xffffffffu, v, o);
    return v;
}

__device__ __forceinline__ float warpdot512(const float* __restrict__ a,
                                            const float* __restrict__ b, int lane) {
    float s = 0.f;
#pragma unroll
    for (int c = 0; c < 4; c++) {
        float4 av = *(const float4*)(a + c * 128 + lane * 4);
        float4 bv = *(const float4*)(b + c * 128 + lane * 4);
        s += av.x * bv.x + av.y * bv.y + av.z * bv.z + av.w * bv.w;
    }
    return s;
}

// ---------------- persistent recurrence kernel ----------------
__global__ void __launch_bounds__(NTHR) recurrence_kernel(
    const float* __restrict__ features, const int* __restrict__ captions,
    const float* __restrict__ embed_W,
    const float* __restrict__ ihW, const float* __restrict__ ihb,
    const float* __restrict__ icW, const float* __restrict__ icb,
    const float* __restrict__ rW,  const float* __restrict__ rb,
    const float* __restrict__ Wih, const float* __restrict__ Whh,
    const float* __restrict__ bih, const float* __restrict__ bhh)
{
    const int tid  = threadIdx.x;
    const int lane = tid & 31;
    const int w    = tid >> 5;
    const int gtid = blockIdx.x * NTHR + tid;
    const int wid_g  = gtid >> 5;
    const int nwarps = (NBLK * NTHR) >> 5;
    const int gstride = NBLK * NTHR;

    __shared__ __align__(16) float sh_h[EE];        // 2 KB
    __shared__ float sSc[NREG];
    __shared__ float sh_attn[NREG];
    __shared__ float sh_red[NTHR / 32];
    __shared__ __align__(16) float sPart[16 * 128]; // 8 KB
    __shared__ __align__(16) float sAct[128 * BB];  // 16 KB
    __shared__ __align__(16) float sW[16 * 128];    // 8 KB
    __shared__ __align__(16) float sRed[16 * 4 * BB]; // 8 KB (P4 partials)
    __shared__ float sOut[16 * BB];                 // 2 KB

    // ---- init a: fmean
    for (int idx = gtid; idx < BB * EE; idx += gstride) {
        int b = idx >> 9, e = idx & 511;
        const float* fp = features + (size_t)b * NREG * EE + e;
        float s = 0.f;
        for (int n = 0; n < NREG; n++) s += fp[n * EE];
        g_fmean[idx] = s * (1.0f / NREG);
    }
    gridbar();

    // ---- init b: h0 / c0 (warp per output)
    for (int task = wid_g; task < 2 * BB * HH; task += nwarps) {
        int which = task & 1;
        int m = task >> 1;
        int b = m >> 9, eo = m & 511;
        const float* Wrow = (which ? icW : ihW) + (size_t)eo * EE;
        float s = warpsum(warpdot512(Wrow, g_fmean + b * EE, lane));
        if (lane == 0) {
            if (which) {
                g_cT[eo * BB + b] = s + icb[eo];
            } else {
                float hv = s + ihb[eo];
                g_hbuf[0][m] = hv;
                g_hT[0][eo * BB + b] = hv;
            }
        }
    }
    gridbar();

    for (int t = 0; t < SEQ; t++) {
        const float* h_cur  = g_hbuf[t & 1];
        const float* hT_cur = g_hT[t & 1];
        float*       h_nxt  = g_hbuf[(t & 1) ^ 1];
        float*       hT_nxt = g_hT[(t & 1) ^ 1];

        // ==== P12 (R8 version): attention, scores redundant per (b,chunk) block
        if (blockIdx.x < 128) {
            const int b = blockIdx.x >> 2;
            const int chunk = blockIdx.x & 3;
            const float* fb = features + (size_t)b * NREG * EE;

            sh_h[tid] = h_cur[b * EE + tid];
            __syncthreads();

            for (int n = w; n < NREG; n += 16) {
                float s = warpsum(warpdot512(fb + (size_t)n * EE, sh_h, lane));
                if (lane == 0) sSc[n] = s;
            }
            __syncthreads();

            float v = (tid < NREG) ? sSc[tid] : -1e30f;
            float m = v;
#pragma unroll
            for (int o = 16; o; o >>= 1) m = fmaxf(m, __shfl_xor_sync(0xffffffffu, m, o));
            if (lane == 0) sh_red[w] = m;
            __syncthreads();
            float mx = sh_red[0];
#pragma unroll
            for (int i = 1; i < 16; i++) mx = fmaxf(mx, sh_red[i]);
            float ev = (tid < NREG) ? __expf(v - mx) : 0.f;
            float ps = warpsum(ev);
            __syncthreads();
            if (lane == 0) sh_red[w] = ps;
            __syncthreads();
            float tot = 0.f;
#pragma unroll
            for (int i = 0; i < 16; i++) tot += sh_red[i];
            if (tid < NREG) sh_attn[tid] = ev / tot;
            __syncthreads();

            float4 cacc = make_float4(0.f, 0.f, 0.f, 0.f);
            const float* fc = fb + chunk * 128 + lane * 4;
#pragma unroll 4
            for (int n = w; n < NREG; n += 16) {
                float a = sh_attn[n];
                float4 fv = *(const float4*)(fc + (size_t)n * EE);
                cacc.x += a * fv.x; cacc.y += a * fv.y;
                cacc.z += a * fv.z; cacc.w += a * fv.w;
            }
            *(float4*)(sPart + w * 128 + lane * 4) = cacc;
            __syncthreads();
            if (tid < 128) {
                float s = 0.f;
#pragma unroll
                for (int i = 0; i < 16; i++) s += sPart[i * 128 + tid];
                g_actCE[(chunk * 128 + tid) * BB + b] = s;
            }
        } else {
            for (int idx = (blockIdx.x - 128) * NTHR + tid; idx < BB * EE;
                 idx += 20 * NTHR) {
                int b = idx >> 9, k = idx & 511;
                int tok = captions[b * SEQ + t];
                g_actCE[(EE + k) * BB + b] =
                    embed_W[(size_t)tok * EE + k] * 22.62741699796952f; // sqrt(512)
            }
        }
        gridbar();

        // ==== P3 (R8 version): x = rW @ [ctx; emb] + rb
        if (blockIdx.x < 128) {
            const int r0 = blockIdx.x * 4;
            const int row = w >> 2, q = w & 3;
            float acc = 0.f;
            for (int kc = 0; kc < 8; kc++) {
                __syncthreads();
                const float* asrc = g_actCE + kc * 128 * BB;
                for (int i4 = tid; i4 < 1024; i4 += NTHR)
                    ((float4*)sAct)[i4] = ((const float4*)asrc)[i4];
                {
                    int r = tid >> 7, k = tid & 127;
                    sW[tid] = rW[(size_t)(r0 + r) * (EE + HH) + kc * 128 + k];
                }
                __syncthreads();
                const float* wp = sW + row * 128 + q * 32;
#pragma unroll
                for (int k = 0; k < 32; k += 4) {
                    float4 wv = *(const float4*)(wp + k);
                    const float* ap = sAct + (q * 32 + k) * BB + lane;
                    acc += wv.x * ap[0 * BB];
                    acc += wv.y * ap[1 * BB];
                    acc += wv.z * ap[2 * BB];
                    acc += wv.w * ap[3 * BB];
                }
            }
            sOut[(row * 4 + q) * BB + lane] = acc;
            __syncthreads();
            if (tid < 128) {
                int r = tid >> 5, b = tid & 31;
                float s = sOut[(r * 4 + 0) * BB + b] + sOut[(r * 4 + 1) * BB + b]
                        + sOut[(r * 4 + 2) * BB + b] + sOut[(r * 4 + 3) * BB + b];
                g_actX[(r0 + r) * BB + b] = s + rb[r0 + r];
            }
        }
        gridbar();

        // ==== P4 (R9 version): register-blocked — warp = (4-row group, k-quarter)
        if (blockIdx.x < 128) {
            const int rp0 = blockIdx.x * 16;
            const int rg = w >> 2, qq = w & 3;
            float acc0 = 0.f, acc1 = 0.f, acc2 = 0.f, acc3 = 0.f;
            for (int kc = 0; kc < 8; kc++) {
                __syncthreads();
                const float* asrc = (kc < 4) ? (g_actX + kc * 128 * BB)
                                             : (hT_cur + (kc - 4) * 128 * BB);
                for (int i4 = tid; i4 < 1024; i4 += NTHR)
                    ((float4*)sAct)[i4] = ((const float4*)asrc)[i4];
#pragma unroll
                for (int s = 0; s < 4; s++) {
                    int i = tid + s * NTHR;
                    int rl = i >> 7, k = i & 127;
                    int rp = rp0 + rl;
                    int hi = rp >> 2, gate = rp & 3;
                    sW[i] = (kc < 4)
                        ? Wih[(size_t)(gate * HH + hi) * EE + kc * 128 + k]
                        : Whh[(size_t)(gate * HH + hi) * HH + (kc - 4) * 128 + k];
                }
                __syncthreads();
                const float* w0p = sW + (rg * 4 + 0) * 128 + qq * 32;
                const float* w1p = sW + (rg * 4 + 1) * 128 + qq * 32;
                const float* w2p = sW + (rg * 4 + 2) * 128 + qq * 32;
                const float* w3p = sW + (rg * 4 + 3) * 128 + qq * 32;
#pragma unroll
                for (int k4 = 0; k4 < 32; k4 += 4) {
                    const float* ap = sAct + (qq * 32 + k4) * BB + lane;
                    float a0 = ap[0 * BB], a1 = ap[1 * BB];
                    float a2 = ap[2 * BB], a3 = ap[3 * BB];
                    float4 w0 = *(const float4*)(w0p + k4);
                    float4 w1 = *(const float4*)(w1p + k4);
                    float4 w2 = *(const float4*)(w2p + k4);
                    float4 w3 = *(const float4*)(w3p + k4);
                    acc0 += w0.x * a0 + w0.y * a1 + w0.z * a2 + w0.w * a3;
                    acc1 += w1.x * a0 + w1.y * a1 + w1.z * a2 + w1.w * a3;
                    acc2 += w2.x * a0 + w2.y * a1 + w2.z * a2 + w2.w * a3;
                    acc3 += w3.x * a0 + w3.y * a1 + w3.z * a2 + w3.w * a3;
                }
            }
            sRed[((rg * 4 + 0) * 4 + qq) * BB + lane] = acc0;
            sRed[((rg * 4 + 1) * 4 + qq) * BB + lane] = acc1;
            sRed[((rg * 4 + 2) * 4 + qq) * BB + lane] = acc2;
            sRed[((rg * 4 + 3) * 4 + qq) * BB + lane] = acc3;
            __syncthreads();
            {
                int rl = tid >> 5, b = tid & 31;
                float s = sRed[(rl * 4 + 0) * BB + b] + sRed[(rl * 4 + 1) * BB + b]
                        + sRed[(rl * 4 + 2) * BB + b] + sRed[(rl * 4 + 3) * BB + b];
                sOut[rl * BB + b] = s;
            }
            __syncthreads();
            if (tid < 128) {
                int hl = tid >> 5;
                int b  = tid & 31;
                int hi = blockIdx.x * 4 + hl;
                float iv = sOut[(hl * 4 + 0) * BB + b] + bih[hi]          + bhh[hi];
                float fv = sOut[(hl * 4 + 1) * BB + b] + bih[HH + hi]     + bhh[HH + hi];
                float gv = sOut[(hl * 4 + 2) * BB + b] + bih[2 * HH + hi] + bhh[2 * HH + hi];
                float ov = sOut[(hl * 4 + 3) * BB + b] + bih[3 * HH + hi] + bhh[3 * HH + hi];
                float si = 1.f / (1.f + __expf(-iv));
                float sf = 1.f / (1.f + __expf(-fv));
                float so = 1.f / (1.f + __expf(-ov));
                float c2 = sf * g_cT[hi * BB + b] + si * tanhf(gv);
                float h2 = so * tanhf(c2);
                g_cT[hi * BB + b] = c2;
                hT_nxt[hi * BB + b] = h2;
                h_nxt[b * HH + hi] = h2;
                g_Hall[((size_t)t * BB + b) * HH + hi] = h2;
            }
        }
        gridbar();
    }
}

// ---------------- fp32 -> bf16 hi/lo split ----------------
__device__ __forceinline__ void split_store(float4 v, __nv_bfloat16* H,
                                            __nv_bfloat16* L, size_t off) {
    __nv_bfloat162 h0, h1, l0, l1;
    h0.x = __float2bfloat16(v.x); h0.y = __float2bfloat16(v.y);
    h1.x = __float2bfloat16(v.z); h1.y = __float2bfloat16(v.w);
    l0.x = __float2bfloat16(v.x - __bfloat162float(h0.x));
    l0.y = __float2bfloat16(v.y - __bfloat162float(h0.y));
    l1.x = __float2bfloat16(v.z - __bfloat162float(h1.x));
    l1.y = __float2bfloat16(v.w - __bfloat162float(h1.y));
    *(__nv_bfloat162*)(H + off) = h0; *(__nv_bfloat162*)(H + off + 2) = h1;
    *(__nv_bfloat162*)(L + off) = l0; *(__nv_bfloat162*)(L + off + 2) = l1;
}

__global__ void __launch_bounds__(256) convert_kernel(const float* __restrict__ outW)
{
    const size_t NW4 = ((size_t)VV * EE) / 4;
    const size_t NA4 = ((size_t)SEQ * BB * HH) / 4;
    size_t stride = (size_t)gridDim.x * blockDim.x;
    for (size_t i = (size_t)blockIdx.x * blockDim.x + threadIdx.x;
         i < NW4 + NA4; i += stride) {
        if (i < NW4) {
            float4 v = ((const float4*)outW)[i];
            split_store(v, g_WH, g_WL, i * 4);
        } else {
            size_t j = i - NW4;
            float4 v = ((const float4*)g_Hall)[j];
            split_store(v, g_AH, g_AL, j * 4);
        }
    }
}

// ---------------- tensor-core output GEMM ----------------
#define LDSW 40  // padded smem row stride (bf16 elems)

__device__ __forceinline__ uint32_t s2u(const void* p) {
    return (uint32_t)__cvta_generic_to_shared(p);
}
__device__ __forceinline__ void ldsm_x4(uint32_t r[4], uint32_t addr) {
    asm volatile("ldmatrix.sync.aligned.m8n8.x4.shared.b16 {%0,%1,%2,%3}, [%4];"
                 : "=r"(r[0]), "=r"(r[1]), "=r"(r[2]), "=r"(r[3]) : "r"(addr));
}
__device__ __forceinline__ void mma_bf16(float c[4], const uint32_t a[4], const uint32_t b[2]) {
    asm volatile("mma.sync.aligned.m16n8k16.row.col.f32.bf16.bf16.f32 "
                 "{%0,%1,%2,%3}, {%4,%5,%6,%7}, {%8,%9}, {%0,%1,%2,%3};"
                 : "+f"(c[0]), "+f"(c[1]), "+f"(c[2]), "+f"(c[3])
                 : "r"(a[0]), "r"(a[1]), "r"(a[2]), "r"(a[3]), "r"(b[0]), "r"(b[1]));
}

__global__ void __launch_bounds__(256) out_gemm_tc(
    const float* __restrict__ outb, float* __restrict__ out)
{
    __shared__ __align__(16) __nv_bfloat16 sAH[128 * LDSW];
    __shared__ __align__(16) __nv_bfloat16 sAL[128 * LDSW];
    __shared__ __align__(16) __nv_bfloat16 sBH[128 * LDSW];
    __shared__ __align__(16) __nv_bfloat16 sBL[128 * LDSW];

    const int tid  = threadIdx.x;
    const int lane = tid & 31;
    const int w    = tid >> 5;
    const int wm   = w >> 2;
    const int wn   = w & 3;
    const int m0 = blockIdx.y * 128;
    const int n0 = blockIdx.x * 128;

    float acc[4][4][4];
#pragma unroll
    for (int mt = 0; mt < 4; mt++)
#pragma unroll
        for (int nt = 0; nt < 4; nt++)
#pragma unroll
            for (int r = 0; r < 4; r++) acc[mt][nt][r] = 0.f;

    const int a_row = lane & 15;
    const int a_k8  = (lane >> 4) * 8;
    const int b_nrw = (lane & 7) + ((lane >> 4) << 3);
    const int b_k8  = ((lane >> 3) & 1) * 8;

    const uint32_t uAH = s2u(sAH), uAL = s2u(sAL);
    const uint32_t uBH = s2u(sBH), uBL = s2u(sBL);

    for (int k0 = 0; k0 < 512; k0 += 32) {
        __syncthreads();
#pragma unroll
        for (int i = 0; i < 2; i++) {
            int v = tid + i * 256;
            int row = v >> 2;
            int kc  = (v & 3) * 8;
            size_t ga = (size_t)(m0 + row) * 512 + k0 + kc;
            size_t gb = (size_t)(n0 + row) * 512 + k0 + kc;
            int so = row * LDSW + kc;
            *(uint4*)(sAH + so) = *(const uint4*)(g_AH + ga);
            *(uint4*)(sAL + so) = *(const uint4*)(g_AL + ga);
            *(uint4*)(sBH + so) = *(const uint4*)(g_WH + gb);
            *(uint4*)(sBL + so) = *(const uint4*)(g_WL + gb);
        }
        __syncthreads();

#pragma unroll
        for (int ks = 0; ks < 32; ks += 16) {
            uint32_t aH[4][4], aL[4][4];
#pragma unroll
            for (int mt = 0; mt < 4; mt++) {
                int off = ((wm * 64 + mt * 16 + a_row) * LDSW + ks + a_k8) * 2;
                ldsm_x4(aH[mt], uAH + off);
                ldsm_x4(aL[mt], uAL + off);
            }
            uint32_t bH[4][2], bL[4][2];
#pragma unroll
            for (int p = 0; p < 2; p++) {
                int off = ((wn * 32 + p * 16 + b_nrw) * LDSW + ks + b_k8) * 2;
                uint32_t r[4];
                ldsm_x4(r, uBH + off);
                bH[2 * p][0] = r[0]; bH[2 * p][1] = r[1];
                bH[2 * p + 1][0] = r[2]; bH[2 * p + 1][1] = r[3];
                ldsm_x4(r, uBL + off);
                bL[2 * p][0] = r[0]; bL[2 * p][1] = r[1];
                bL[2 * p + 1][0] = r[2]; bL[2 * p + 1][1] = r[3];
            }
#pragma unroll
            for (int mt = 0; mt < 4; mt++)
#pragma unroll
                for (int nt = 0; nt < 4; nt++) {
                    mma_bf16(acc[mt][nt], aH[mt], bH[nt]);
                    mma_bf16(acc[mt][nt], aH[mt], bL[nt]);
                    mma_bf16(acc[mt][nt], aL[mt], bH[nt]);
                }
        }
    }

#pragma unroll
    for (int mt = 0; mt < 4; mt++) {
#pragma unroll
        for (int half = 0; half < 2; half++) {
            int m = m0 + wm * 64 + mt * 16 + (lane >> 2) + half * 8;
            int tt = m >> 5, b = m & 31;
            float* orow = out + ((size_t)b * SEQ + tt) * VV;
#pragma unroll
            for (int nt = 0; nt < 4; nt++) {
                int n = n0 + wn * 32 + nt * 8 + 2 * (lane & 3);
                float2 bias = *(const float2*)(outb + n);
                float2 v;
                v.x = acc[mt][nt][2 * half + 0] + bias.x;
                v.y = acc[mt][nt][2 * half + 1] + bias.y;
                *(float2*)(orow + n) = v;
            }
        }
    }
}

extern "C" void kernel_launch(void* const* d_in, const int* in_sizes, int n_in,
                              void* d_out, int out_size)
{
    const float* features = (const float*)d_in[0];
    const int*   captions = (const int*)d_in[1];
    const float* embed_W  = (const float*)d_in[2];
    const float* ihW = (const float*)d_in[3];
    const float* ihb = (const float*)d_in[4];
    const float* icW = (const float*)d_in[5];
    const float* icb = (const float*)d_in[6];
    const float* rW  = (const float*)d_in[7];
    const float* rb  = (const float*)d_in[8];
    const float* Wih = (const float*)d_in[9];
    const float* Whh = (const float*)d_in[10];
    const float* bih = (const float*)d_in[11];
    const float* bhh = (const float*)d_in[12];
    const float* outW = (const float*)d_in[13];
    const float* outb = (const float*)d_in[14];

    recurrence_kernel<<<NBLK, NTHR>>>(features, captions, embed_W,
                                      ihW, ihb, icW, icb, rW, rb,
                                      Wih, Whh, bih, bhh);
    convert_kernel<<<2048, 256>>>(outW);
    dim3 grid(VV / 128, (SEQ * BB) / 128);
    out_gemm_tc<<<grid, 256>>>(outb, (float*)d_out);
}